// round 11
// baseline (speedup 1.0000x reference)
#include <cuda_runtime.h>

#define NB   32      // batch
#define SD   24      // channels
#define H1   32      // conv1 out spatial
#define H2   16      // conv2 out spatial
#define RQ   128
#define MD   128
#define FC   1024

// ---------------- scratch (device globals: no allocation allowed) ----------
__device__ float g_y1[NB*SD*H1*H1];          // conv1 pre-BN output (3 MB)
__device__ float g_y2[NB*SD*H2*H2];          // conv2 pre-BN output
__device__ float g_p1s[SD*NB], g_p1q[SD*NB]; // BN1 partial sums / sumsq per (c,n)
__device__ float g_p2s[SD*NB], g_p2q[SD*NB]; // BN2 partials
__device__ float g_a1[SD], g_c1[SD];         // folded BN1 scale/shift
__device__ float g_a2[SD], g_c2[SD];         // folded BN2 scale/shift
__device__ float g_rel[NB*MD];               // relations

// ---------------- K1: conv1 (3->24, 3x3, stride2, pad1) + BN1 partials ----
// grid (6 channel-groups, 32 n), 256 threads
// dynamic smem: image padded 3*65*65 + weights 108 + bias 4 = 12787 floats
extern "C" __global__ void __launch_bounds__(256)
conv1_k(const float* __restrict__ img, const float* __restrict__ w,
        const float* __restrict__ b) {
    extern __shared__ float sm[];
    float* simg = sm;             // 3 planes of 65x65, row/col 0 are zero pad
    float* sw   = sm + 3*4225;    // 4 oc * 27
    float* sb   = sw + 108;       // 4
    const int tid = threadIdx.x;
    const int cg = blockIdx.x, n = blockIdx.y;
    const int cbase = cg * 4;

    // zero top/left pad borders: 129 entries per plane
    for (int i = tid; i < 387; i += 256) {
        int pl = i / 129, r = i - pl * 129;
        if (r < 65) simg[pl*4225 + r] = 0.f;
        else        simg[pl*4225 + (r-64)*65] = 0.f;
    }
    // load image[n]: 3*64*64 floats via float4
    const float4* im4 = reinterpret_cast<const float4*>(img) + (size_t)n * 3072;
    for (int i = tid; i < 3072; i += 256) {
        int c = i >> 10, rem = i & 1023;
        int y = rem >> 4, x4 = rem & 15;
        float4 v = im4[i];
        float* d = simg + c*4225 + (y+1)*65 + x4*4 + 1;
        d[0]=v.x; d[1]=v.y; d[2]=v.z; d[3]=v.w;
    }
    if (tid < 108) sw[tid] = w[cbase*27 + tid];
    if (tid < 4)   sb[tid] = b[cbase + tid];
    __syncthreads();

    float ls[4] = {0,0,0,0}, lq[4] = {0,0,0,0};
    #pragma unroll
    for (int k = 0; k < 4; k++) {
        int p = tid + k*256;
        int oy = p >> 5, ox = p & 31;
        float in[27];
        #pragma unroll
        for (int ic = 0; ic < 3; ic++) {
            const float* sp = simg + ic*4225 + (2*oy)*65 + 2*ox;
            #pragma unroll
            for (int ky = 0; ky < 3; ky++)
                #pragma unroll
                for (int kx = 0; kx < 3; kx++)
                    in[ic*9 + ky*3 + kx] = sp[ky*65 + kx];
        }
        #pragma unroll
        for (int oc = 0; oc < 4; oc++) {
            float acc = sb[oc];
            #pragma unroll
            for (int t = 0; t < 27; t++) acc = fmaf(in[t], sw[oc*27 + t], acc);
            g_y1[(size_t)(n*SD + cbase + oc)*1024 + p] = acc;
            ls[oc] += acc; lq[oc] += acc*acc;
        }
    }
    // deterministic block reduce of 8 values
    __shared__ float red[64];
    float v8[8] = {ls[0],ls[1],ls[2],ls[3], lq[0],lq[1],lq[2],lq[3]};
    #pragma unroll
    for (int i = 0; i < 8; i++) {
        float v = v8[i];
        #pragma unroll
        for (int o = 16; o; o >>= 1) v += __shfl_down_sync(0xffffffffu, v, o);
        v8[i] = v;
    }
    int lane = tid & 31, wp = tid >> 5;
    if (lane == 0)
        #pragma unroll
        for (int i = 0; i < 8; i++) red[wp*8 + i] = v8[i];
    __syncthreads();
    if (tid < 8) {
        float r = 0.f;
        #pragma unroll
        for (int wq = 0; wq < 8; wq++) r += red[wq*8 + tid];
        if (tid < 4) g_p1s[(cbase + tid)*NB + n] = r;
        else         g_p1q[(cbase + tid - 4)*NB + n] = r;
    }
}

// ---------------- K2/K4: finalize BN stats -> folded scale/shift ----------
extern "C" __global__ void bnfin_k(const float* __restrict__ g,
                                   const float* __restrict__ be, int which) {
    int c = threadIdx.x;
    if (c >= SD) return;
    const float* ps = which ? g_p2s : g_p1s;
    const float* pq = which ? g_p2q : g_p1q;
    float inv = which ? (1.f/8192.f) : (1.f/32768.f);
    float s = 0.f, q = 0.f;
    for (int n = 0; n < NB; n++) { s += ps[c*NB + n]; q += pq[c*NB + n]; }
    float mu  = s * inv;
    float var = q * inv - mu*mu;
    float rs  = rsqrtf(var + 1e-5f);
    float a   = rs * g[c];
    float sh  = be[c] - mu * a;
    if (which) { g_a2[c] = a; g_c2[c] = sh; }
    else       { g_a1[c] = a; g_c1[c] = sh; }
}

// ---------------- K3: conv2 (24->24) with BN1+ReLU applied on load --------
// grid (6 oc-groups, 32 n), 256 threads
// dynamic smem: 24 planes 33x33 (26136) + weights 864 + a/c 48 = 27048 floats
extern "C" __global__ void __launch_bounds__(256)
conv2_k(const float* __restrict__ w, const float* __restrict__ b) {
    extern __shared__ float sm[];
    float* sinp = sm;                 // 24 * 1089 padded planes
    float* sw   = sm + 24*1089;       // 864
    float* sa   = sw + 864;           // 24
    float* sc   = sa + 24;            // 24
    const int tid = threadIdx.x;
    const int cg = blockIdx.x, n = blockIdx.y;
    const int cbase = cg * 4;

    if (tid < 24) { sa[tid] = g_a1[tid]; sc[tid] = g_c1[tid]; }
    for (int i = tid; i < 1560; i += 256) {           // zero pad borders
        int pl = i / 65, r = i - pl * 65;
        if (r < 33) sinp[pl*1089 + r] = 0.f;
        else        sinp[pl*1089 + (r-32)*33] = 0.f;
    }
    __syncthreads();   // sa/sc ready

    const float* y1 = g_y1 + (size_t)n * SD * 1024;
    for (int i = tid; i < SD*1024; i += 256) {
        int c = i >> 10, rem = i & 1023;
        int y = rem >> 5, x = rem & 31;
        float v = fmaxf(fmaf(y1[i], sa[c], sc[c]), 0.f);  // BN1 + ReLU
        sinp[c*1089 + (y+1)*33 + x + 1] = v;
    }
    for (int i = tid; i < 864; i += 256) sw[i] = w[cbase*216 + i];
    __syncthreads();

    int oy = tid >> 4, ox = tid & 15;     // one output position per thread
    float acc[4];
    #pragma unroll
    for (int oc = 0; oc < 4; oc++) acc[oc] = b[cbase + oc];
    #pragma unroll 4
    for (int ic = 0; ic < SD; ic++) {
        const float* sp = sinp + ic*1089 + (2*oy)*33 + 2*ox;
        float in[9];
        #pragma unroll
        for (int ky = 0; ky < 3; ky++)
            #pragma unroll
            for (int kx = 0; kx < 3; kx++) in[ky*3 + kx] = sp[ky*33 + kx];
        #pragma unroll
        for (int oc = 0; oc < 4; oc++) {
            const float* wp = sw + oc*216 + ic*9;
            #pragma unroll
            for (int t = 0; t < 9; t++) acc[oc] = fmaf(in[t], wp[t], acc[oc]);
        }
    }
    float ls[4], lq[4];
    #pragma unroll
    for (int oc = 0; oc < 4; oc++) {
        g_y2[(size_t)(n*SD + cbase + oc)*256 + tid] = acc[oc];
        ls[oc] = acc[oc]; lq[oc] = acc[oc]*acc[oc];
    }
    __shared__ float red[64];
    float v8[8] = {ls[0],ls[1],ls[2],ls[3], lq[0],lq[1],lq[2],lq[3]};
    #pragma unroll
    for (int i = 0; i < 8; i++) {
        float v = v8[i];
        #pragma unroll
        for (int o = 16; o; o >>= 1) v += __shfl_down_sync(0xffffffffu, v, o);
        v8[i] = v;
    }
    int lane = tid & 31, wp2 = tid >> 5;
    if (lane == 0)
        #pragma unroll
        for (int i = 0; i < 8; i++) red[wp2*8 + i] = v8[i];
    __syncthreads();
    if (tid < 8) {
        float r = 0.f;
        #pragma unroll
        for (int wq = 0; wq < 8; wq++) r += red[wq*8 + tid];
        if (tid < 4) g_p2s[(cbase + tid)*NB + n] = r;
        else         g_p2q[(cbase + tid - 4)*NB + n] = r;
    }
}

// ---------------- K5: channel sums s + relations ---------------------------
// grid 32 (per n), 128 threads
// rel[n,j] = 256*sum_c s[c]*(Wi+Wj)[c,j] + 65536*(ques[n]@Wq[:,j] + b_rel[j])
// coords sum to 0 over the symmetric linspace -> s[24]=s[25]=0.
extern "C" __global__ void __launch_bounds__(128)
rel_k(const float* __restrict__ ques, const float* __restrict__ w_rel,
      const float* __restrict__ b_rel) {
    __shared__ float s[26];
    __shared__ float q[RQ];
    const int n = blockIdx.x, tid = threadIdx.x;
    const int lane = tid & 31, wp = tid >> 5;

    for (int c = wp; c < SD; c += 4) {
        const float* yp = g_y2 + (size_t)(n*SD + c)*256;
        float a = g_a2[c], sh = g_c2[c];
        float v = 0.f;
        #pragma unroll
        for (int i = lane; i < 256; i += 32)
            v += fmaxf(fmaf(yp[i], a, sh), 0.f);     // BN2 + ReLU
        #pragma unroll
        for (int o = 16; o; o >>= 1) v += __shfl_down_sync(0xffffffffu, v, o);
        if (lane == 0) s[c] = v;
    }
    if (tid == 0) { s[24] = 0.f; s[25] = 0.f; }
    q[tid] = ques[n*RQ + tid];
    __syncthreads();

    const int j = tid;
    float r = b_rel[j];
    #pragma unroll 8
    for (int k = 0; k < RQ; k++)
        r = fmaf(q[k], w_rel[(52 + k)*MD + j], r);   // Wq rows 52..179
    float t = 0.f;
    #pragma unroll
    for (int c = 0; c < 26; c++)
        t = fmaf(s[c], w_rel[c*MD + j] + w_rel[(26 + c)*MD + j], t);
    g_rel[n*MD + j] = fmaf(65536.f, r, 256.f * t);
}

// ---------------- K6: fc1 (relu) + fc2 fused -------------------------------
// grid 32 (per n), 1024 threads: one fc1 output per thread, block-reduce fc2
extern "C" __global__ void __launch_bounds__(1024)
fc_k(const float* __restrict__ w_fc1, const float* __restrict__ b_fc1,
     const float* __restrict__ w_fc2, const float* __restrict__ b_fc2,
     float* __restrict__ out) {
    __shared__ float rel[MD];
    __shared__ float r0[32], r1[32];
    const int n = blockIdx.x, tid = threadIdx.x;
    if (tid < MD) rel[tid] = g_rel[n*MD + tid];
    __syncthreads();

    float h = b_fc1[tid];
    #pragma unroll 16
    for (int k = 0; k < MD; k++)
        h = fmaf(rel[k], w_fc1[k*FC + tid], h);      // coalesced across tid
    h = fmaxf(h, 0.f);
    float a0 = h * w_fc2[tid*2 + 0];
    float a1 = h * w_fc2[tid*2 + 1];
    #pragma unroll
    for (int o = 16; o; o >>= 1) {
        a0 += __shfl_down_sync(0xffffffffu, a0, o);
        a1 += __shfl_down_sync(0xffffffffu, a1, o);
    }
    const int lane = tid & 31, wp = tid >> 5;
    if (lane == 0) { r0[wp] = a0; r1[wp] = a1; }
    __syncthreads();
    if (tid < 32) {
        float v0 = r0[tid], v1 = r1[tid];
        #pragma unroll
        for (int o = 16; o; o >>= 1) {
            v0 += __shfl_down_sync(0xffffffffu, v0, o);
            v1 += __shfl_down_sync(0xffffffffu, v1, o);
        }
        if (tid == 0) {
            out[n*2 + 0] = v0 + b_fc2[0];
            out[n*2 + 1] = v1 + b_fc2[1];
        }
    }
}

// ---------------- launch ----------------------------------------------------
extern "C" void kernel_launch(void* const* d_in, const int* in_sizes, int n_in,
                              void* d_out, int out_size) {
    const float* image   = (const float*)d_in[0];
    const float* ques    = (const float*)d_in[1];
    const float* conv1_w = (const float*)d_in[2];
    const float* conv1_b = (const float*)d_in[3];
    const float* bn1_g   = (const float*)d_in[4];
    const float* bn1_b   = (const float*)d_in[5];
    const float* conv2_w = (const float*)d_in[6];
    const float* conv2_b = (const float*)d_in[7];
    const float* bn2_g   = (const float*)d_in[8];
    const float* bn2_b   = (const float*)d_in[9];
    const float* w_rel   = (const float*)d_in[10];
    const float* b_rel   = (const float*)d_in[11];
    const float* w_fc1   = (const float*)d_in[12];
    const float* b_fc1   = (const float*)d_in[13];
    const float* w_fc2   = (const float*)d_in[14];
    const float* b_fc2   = (const float*)d_in[15];

    const int SM1 = (3*4225 + 108 + 4) * 4;        // 51148 B
    const int SM3 = (24*1089 + 864 + 48) * 4;      // 108192 B
    cudaFuncSetAttribute(conv1_k, cudaFuncAttributeMaxDynamicSharedMemorySize, SM1);
    cudaFuncSetAttribute(conv2_k, cudaFuncAttributeMaxDynamicSharedMemorySize, SM3);

    conv1_k<<<dim3(6, 32), 256, SM1>>>(image, conv1_w, conv1_b);
    bnfin_k<<<1, 32>>>(bn1_g, bn1_b, 0);
    conv2_k<<<dim3(6, 32), 256, SM3>>>(conv2_w, conv2_b);
    bnfin_k<<<1, 32>>>(bn2_g, bn2_b, 1);
    rel_k<<<32, 128>>>(ques, w_rel, b_rel);
    fc_k<<<32, 1024>>>(w_fc1, b_fc1, w_fc2, b_fc2, (float*)d_out);
}

// round 12
// speedup vs baseline: 1.0059x; 1.0059x over previous
#include <cuda_runtime.h>

#define NB   32      // batch
#define SD   24      // channels
#define H1   32      // conv1 out spatial
#define H2   16      // conv2 out spatial
#define RQ   128
#define MD   128
#define FC   1024

// ---------------- scratch (device globals: no allocation allowed) ----------
__device__ float g_y1[NB*SD*H1*H1];          // conv1 pre-BN output (3 MB)
__device__ float g_y2[NB*SD*H2*H2];          // conv2 pre-BN output
__device__ float g_p1s[SD*NB], g_p1q[SD*NB]; // BN1 partial sums / sumsq per (c,n)
__device__ float g_p2s[SD*NB], g_p2q[SD*NB]; // BN2 partials
__device__ float g_a1[SD], g_c1[SD];         // folded BN1 scale/shift
__device__ float g_a2[SD], g_c2[SD];         // folded BN2 scale/shift
__device__ float g_rel[NB*MD];               // relations

// ---------------- K1: conv1 (3->24, 3x3, stride2, pad1) + BN1 partials ----
// grid (6 channel-groups, 32 n), 256 threads
// dynamic smem: image padded 3*65*65 + weights 108 + bias 4 = 12787 floats
extern "C" __global__ void __launch_bounds__(256)
conv1_k(const float* __restrict__ img, const float* __restrict__ w,
        const float* __restrict__ b) {
    extern __shared__ float sm[];
    float* simg = sm;             // 3 planes of 65x65, row/col 0 are zero pad
    float* sw   = sm + 3*4225;    // 4 oc * 27
    float* sb   = sw + 108;       // 4
    const int tid = threadIdx.x;
    const int cg = blockIdx.x, n = blockIdx.y;
    const int cbase = cg * 4;

    // zero top/left pad borders: 129 entries per plane
    for (int i = tid; i < 387; i += 256) {
        int pl = i / 129, r = i - pl * 129;
        if (r < 65) simg[pl*4225 + r] = 0.f;
        else        simg[pl*4225 + (r-64)*65] = 0.f;
    }
    // load image[n]: 3*64*64 floats via float4
    const float4* im4 = reinterpret_cast<const float4*>(img) + (size_t)n * 3072;
    for (int i = tid; i < 3072; i += 256) {
        int c = i >> 10, rem = i & 1023;
        int y = rem >> 4, x4 = rem & 15;
        float4 v = im4[i];
        float* d = simg + c*4225 + (y+1)*65 + x4*4 + 1;
        d[0]=v.x; d[1]=v.y; d[2]=v.z; d[3]=v.w;
    }
    if (tid < 108) sw[tid] = w[cbase*27 + tid];
    if (tid < 4)   sb[tid] = b[cbase + tid];
    __syncthreads();

    float ls[4] = {0,0,0,0}, lq[4] = {0,0,0,0};
    #pragma unroll
    for (int k = 0; k < 4; k++) {
        int p = tid + k*256;
        int oy = p >> 5, ox = p & 31;
        float in[27];
        #pragma unroll
        for (int ic = 0; ic < 3; ic++) {
            const float* sp = simg + ic*4225 + (2*oy)*65 + 2*ox;
            #pragma unroll
            for (int ky = 0; ky < 3; ky++)
                #pragma unroll
                for (int kx = 0; kx < 3; kx++)
                    in[ic*9 + ky*3 + kx] = sp[ky*65 + kx];
        }
        #pragma unroll
        for (int oc = 0; oc < 4; oc++) {
            float acc = sb[oc];
            #pragma unroll
            for (int t = 0; t < 27; t++) acc = fmaf(in[t], sw[oc*27 + t], acc);
            g_y1[(size_t)(n*SD + cbase + oc)*1024 + p] = acc;
            ls[oc] += acc; lq[oc] += acc*acc;
        }
    }
    // deterministic block reduce of 8 values
    __shared__ float red[64];
    float v8[8] = {ls[0],ls[1],ls[2],ls[3], lq[0],lq[1],lq[2],lq[3]};
    #pragma unroll
    for (int i = 0; i < 8; i++) {
        float v = v8[i];
        #pragma unroll
        for (int o = 16; o; o >>= 1) v += __shfl_down_sync(0xffffffffu, v, o);
        v8[i] = v;
    }
    int lane = tid & 31, wp = tid >> 5;
    if (lane == 0)
        #pragma unroll
        for (int i = 0; i < 8; i++) red[wp*8 + i] = v8[i];
    __syncthreads();
    if (tid < 8) {
        float r = 0.f;
        #pragma unroll
        for (int wq = 0; wq < 8; wq++) r += red[wq*8 + tid];
        if (tid < 4) g_p1s[(cbase + tid)*NB + n] = r;
        else         g_p1q[(cbase + tid - 4)*NB + n] = r;
    }
}

// ---------------- K2/K4: finalize BN stats -> folded scale/shift ----------
extern "C" __global__ void bnfin_k(const float* __restrict__ g,
                                   const float* __restrict__ be, int which) {
    int c = threadIdx.x;
    if (c >= SD) return;
    const float* ps = which ? g_p2s : g_p1s;
    const float* pq = which ? g_p2q : g_p1q;
    float inv = which ? (1.f/8192.f) : (1.f/32768.f);
    float s = 0.f, q = 0.f;
    for (int n = 0; n < NB; n++) { s += ps[c*NB + n]; q += pq[c*NB + n]; }
    float mu  = s * inv;
    float var = q * inv - mu*mu;
    float rs  = rsqrtf(var + 1e-5f);
    float a   = rs * g[c];
    float sh  = be[c] - mu * a;
    if (which) { g_a2[c] = a; g_c2[c] = sh; }
    else       { g_a1[c] = a; g_c1[c] = sh; }
}

// ---------------- K3: conv2 (24->24) with BN1+ReLU applied on load --------
// grid (6 oc-groups, 32 n), 256 threads
// dynamic smem: 24 planes 33x33 (26136) + weights 864 + a/c 48 = 27048 floats
extern "C" __global__ void __launch_bounds__(256)
conv2_k(const float* __restrict__ w, const float* __restrict__ b) {
    extern __shared__ float sm[];
    float* sinp = sm;                 // 24 * 1089 padded planes
    float* sw   = sm + 24*1089;       // 864
    float* sa   = sw + 864;           // 24
    float* sc   = sa + 24;            // 24
    const int tid = threadIdx.x;
    const int cg = blockIdx.x, n = blockIdx.y;
    const int cbase = cg * 4;

    if (tid < 24) { sa[tid] = g_a1[tid]; sc[tid] = g_c1[tid]; }
    for (int i = tid; i < 1560; i += 256) {           // zero pad borders
        int pl = i / 65, r = i - pl * 65;
        if (r < 33) sinp[pl*1089 + r] = 0.f;
        else        sinp[pl*1089 + (r-32)*33] = 0.f;
    }
    __syncthreads();   // sa/sc ready

    const float* y1 = g_y1 + (size_t)n * SD * 1024;
    for (int i = tid; i < SD*1024; i += 256) {
        int c = i >> 10, rem = i & 1023;
        int y = rem >> 5, x = rem & 31;
        float v = fmaxf(fmaf(y1[i], sa[c], sc[c]), 0.f);  // BN1 + ReLU
        sinp[c*1089 + (y+1)*33 + x + 1] = v;
    }
    for (int i = tid; i < 864; i += 256) sw[i] = w[cbase*216 + i];
    __syncthreads();

    int oy = tid >> 4, ox = tid & 15;     // one output position per thread
    float acc[4];
    #pragma unroll
    for (int oc = 0; oc < 4; oc++) acc[oc] = b[cbase + oc];
    #pragma unroll 4
    for (int ic = 0; ic < SD; ic++) {
        const float* sp = sinp + ic*1089 + (2*oy)*33 + 2*ox;
        float in[9];
        #pragma unroll
        for (int ky = 0; ky < 3; ky++)
            #pragma unroll
            for (int kx = 0; kx < 3; kx++) in[ky*3 + kx] = sp[ky*33 + kx];
        #pragma unroll
        for (int oc = 0; oc < 4; oc++) {
            const float* wp = sw + oc*216 + ic*9;
            #pragma unroll
            for (int t = 0; t < 9; t++) acc[oc] = fmaf(in[t], wp[t], acc[oc]);
        }
    }
    float ls[4], lq[4];
    #pragma unroll
    for (int oc = 0; oc < 4; oc++) {
        g_y2[(size_t)(n*SD + cbase + oc)*256 + tid] = acc[oc];
        ls[oc] = acc[oc]; lq[oc] = acc[oc]*acc[oc];
    }
    __shared__ float red[64];
    float v8[8] = {ls[0],ls[1],ls[2],ls[3], lq[0],lq[1],lq[2],lq[3]};
    #pragma unroll
    for (int i = 0; i < 8; i++) {
        float v = v8[i];
        #pragma unroll
        for (int o = 16; o; o >>= 1) v += __shfl_down_sync(0xffffffffu, v, o);
        v8[i] = v;
    }
    int lane = tid & 31, wp2 = tid >> 5;
    if (lane == 0)
        #pragma unroll
        for (int i = 0; i < 8; i++) red[wp2*8 + i] = v8[i];
    __syncthreads();
    if (tid < 8) {
        float r = 0.f;
        #pragma unroll
        for (int wq = 0; wq < 8; wq++) r += red[wq*8 + tid];
        if (tid < 4) g_p2s[(cbase + tid)*NB + n] = r;
        else         g_p2q[(cbase + tid - 4)*NB + n] = r;
    }
}

// ---------------- K5: channel sums s + relations ---------------------------
// grid 32 (per n), 128 threads
// rel[n,j] = 256*sum_c s[c]*(Wi+Wj)[c,j] + 65536*(ques[n]@Wq[:,j] + b_rel[j])
// coords sum to 0 over the symmetric linspace -> s[24]=s[25]=0.
extern "C" __global__ void __launch_bounds__(128)
rel_k(const float* __restrict__ ques, const float* __restrict__ w_rel,
      const float* __restrict__ b_rel) {
    __shared__ float s[26];
    __shared__ float q[RQ];
    const int n = blockIdx.x, tid = threadIdx.x;
    const int lane = tid & 31, wp = tid >> 5;

    for (int c = wp; c < SD; c += 4) {
        const float* yp = g_y2 + (size_t)(n*SD + c)*256;
        float a = g_a2[c], sh = g_c2[c];
        float v = 0.f;
        #pragma unroll
        for (int i = lane; i < 256; i += 32)
            v += fmaxf(fmaf(yp[i], a, sh), 0.f);     // BN2 + ReLU
        #pragma unroll
        for (int o = 16; o; o >>= 1) v += __shfl_down_sync(0xffffffffu, v, o);
        if (lane == 0) s[c] = v;
    }
    if (tid == 0) { s[24] = 0.f; s[25] = 0.f; }
    q[tid] = ques[n*RQ + tid];
    __syncthreads();

    const int j = tid;
    float r = b_rel[j];
    #pragma unroll 8
    for (int k = 0; k < RQ; k++)
        r = fmaf(q[k], w_rel[(52 + k)*MD + j], r);   // Wq rows 52..179
    float t = 0.f;
    #pragma unroll
    for (int c = 0; c < 26; c++)
        t = fmaf(s[c], w_rel[c*MD + j] + w_rel[(26 + c)*MD + j], t);
    g_rel[n*MD + j] = fmaf(65536.f, r, 256.f * t);
}

// ---------------- K6: fc1 (relu) + fc2 fused -------------------------------
// grid 32 (per n), 1024 threads: one fc1 output per thread, block-reduce fc2
extern "C" __global__ void __launch_bounds__(1024)
fc_k(const float* __restrict__ w_fc1, const float* __restrict__ b_fc1,
     const float* __restrict__ w_fc2, const float* __restrict__ b_fc2,
     float* __restrict__ out) {
    __shared__ float rel[MD];
    __shared__ float r0[32], r1[32];
    const int n = blockIdx.x, tid = threadIdx.x;
    if (tid < MD) rel[tid] = g_rel[n*MD + tid];
    __syncthreads();

    float h = b_fc1[tid];
    #pragma unroll 16
    for (int k = 0; k < MD; k++)
        h = fmaf(rel[k], w_fc1[k*FC + tid], h);      // coalesced across tid
    h = fmaxf(h, 0.f);
    float a0 = h * w_fc2[tid*2 + 0];
    float a1 = h * w_fc2[tid*2 + 1];
    #pragma unroll
    for (int o = 16; o; o >>= 1) {
        a0 += __shfl_down_sync(0xffffffffu, a0, o);
        a1 += __shfl_down_sync(0xffffffffu, a1, o);
    }
    const int lane = tid & 31, wp = tid >> 5;
    if (lane == 0) { r0[wp] = a0; r1[wp] = a1; }
    __syncthreads();
    if (tid < 32) {
        float v0 = r0[tid], v1 = r1[tid];
        #pragma unroll
        for (int o = 16; o; o >>= 1) {
            v0 += __shfl_down_sync(0xffffffffu, v0, o);
            v1 += __shfl_down_sync(0xffffffffu, v1, o);
        }
        if (tid == 0) {
            out[n*2 + 0] = v0 + b_fc2[0];
            out[n*2 + 1] = v1 + b_fc2[1];
        }
    }
}

// ---------------- launch ----------------------------------------------------
extern "C" void kernel_launch(void* const* d_in, const int* in_sizes, int n_in,
                              void* d_out, int out_size) {
    const float* image   = (const float*)d_in[0];
    const float* ques    = (const float*)d_in[1];
    const float* conv1_w = (const float*)d_in[2];
    const float* conv1_b = (const float*)d_in[3];
    const float* bn1_g   = (const float*)d_in[4];
    const float* bn1_b   = (const float*)d_in[5];
    const float* conv2_w = (const float*)d_in[6];
    const float* conv2_b = (const float*)d_in[7];
    const float* bn2_g   = (const float*)d_in[8];
    const float* bn2_b   = (const float*)d_in[9];
    const float* w_rel   = (const float*)d_in[10];
    const float* b_rel   = (const float*)d_in[11];
    const float* w_fc1   = (const float*)d_in[12];
    const float* b_fc1   = (const float*)d_in[13];
    const float* w_fc2   = (const float*)d_in[14];
    const float* b_fc2   = (const float*)d_in[15];

    const int SM1 = (3*4225 + 108 + 4) * 4;        // 51148 B
    const int SM3 = (24*1089 + 864 + 48) * 4;      // 108192 B
    cudaFuncSetAttribute(conv1_k, cudaFuncAttributeMaxDynamicSharedMemorySize, SM1);
    cudaFuncSetAttribute(conv2_k, cudaFuncAttributeMaxDynamicSharedMemorySize, SM3);

    conv1_k<<<dim3(6, 32), 256, SM1>>>(image, conv1_w, conv1_b);
    bnfin_k<<<1, 32>>>(bn1_g, bn1_b, 0);
    conv2_k<<<dim3(6, 32), 256, SM3>>>(conv2_w, conv2_b);
    bnfin_k<<<1, 32>>>(bn2_g, bn2_b, 1);
    rel_k<<<32, 128>>>(ques, w_rel, b_rel);
    fc_k<<<32, 1024>>>(w_fc1, b_fc1, w_fc2, b_fc2, (float*)d_out);
}

// round 15
// speedup vs baseline: 1.1105x; 1.1040x over previous
#include <cuda_runtime.h>

#define NB   32      // batch
#define SD   24      // channels
#define H1   32      // conv1 out spatial
#define H2   16      // conv2 out spatial
#define RQ   128
#define MD   128
#define FC   1024

// ---------------- scratch (device globals: no allocation allowed) ----------
__device__ float g_y1[NB*SD*H1*H1];          // conv1 pre-BN output (3 MB)
__device__ float g_y2[NB*SD*H2*H2];          // conv2 pre-BN output
__device__ float g_p1s[SD*NB], g_p1q[SD*NB]; // BN1 partial sums / sumsq per (c,n)
__device__ float g_p2s[SD*NB], g_p2q[SD*NB]; // BN2 partials

// ---------------- K1: conv1 (3->24, 3x3, stride2, pad1) + BN1 partials ----
// grid (6 channel-groups, 32 n), 256 threads
extern "C" __global__ void __launch_bounds__(256)
conv1_k(const float* __restrict__ img, const float* __restrict__ w,
        const float* __restrict__ b) {
    extern __shared__ float sm[];
    float* simg = sm;             // 3 planes of 65x65, row/col 0 are zero pad
    float* sw   = sm + 3*4225;    // 4 oc * 27
    float* sb   = sw + 108;       // 4
    const int tid = threadIdx.x;
    const int cg = blockIdx.x, n = blockIdx.y;
    const int cbase = cg * 4;

    // zero top/left pad borders: 129 entries per plane
    for (int i = tid; i < 387; i += 256) {
        int pl = i / 129, r = i - pl * 129;
        if (r < 65) simg[pl*4225 + r] = 0.f;
        else        simg[pl*4225 + (r-64)*65] = 0.f;
    }
    // load image[n]: 3*64*64 floats via float4
    const float4* im4 = reinterpret_cast<const float4*>(img) + (size_t)n * 3072;
    for (int i = tid; i < 3072; i += 256) {
        int c = i >> 10, rem = i & 1023;
        int y = rem >> 4, x4 = rem & 15;
        float4 v = im4[i];
        float* d = simg + c*4225 + (y+1)*65 + x4*4 + 1;
        d[0]=v.x; d[1]=v.y; d[2]=v.z; d[3]=v.w;
    }
    if (tid < 108) sw[tid] = w[cbase*27 + tid];
    if (tid < 4)   sb[tid] = b[cbase + tid];
    __syncthreads();

    float ls[4] = {0,0,0,0}, lq[4] = {0,0,0,0};
    #pragma unroll
    for (int k = 0; k < 4; k++) {
        int p = tid + k*256;
        int oy = p >> 5, ox = p & 31;
        float in[27];
        #pragma unroll
        for (int ic = 0; ic < 3; ic++) {
            const float* sp = simg + ic*4225 + (2*oy)*65 + 2*ox;
            #pragma unroll
            for (int ky = 0; ky < 3; ky++)
                #pragma unroll
                for (int kx = 0; kx < 3; kx++)
                    in[ic*9 + ky*3 + kx] = sp[ky*65 + kx];
        }
        #pragma unroll
        for (int oc = 0; oc < 4; oc++) {
            float acc = sb[oc];
            #pragma unroll
            for (int t = 0; t < 27; t++) acc = fmaf(in[t], sw[oc*27 + t], acc);
            g_y1[(size_t)(n*SD + cbase + oc)*1024 + p] = acc;
            ls[oc] += acc; lq[oc] += acc*acc;
        }
    }
    // deterministic block reduce of 8 values
    __shared__ float red[64];
    float v8[8] = {ls[0],ls[1],ls[2],ls[3], lq[0],lq[1],lq[2],lq[3]};
    #pragma unroll
    for (int i = 0; i < 8; i++) {
        float v = v8[i];
        #pragma unroll
        for (int o = 16; o; o >>= 1) v += __shfl_down_sync(0xffffffffu, v, o);
        v8[i] = v;
    }
    int lane = tid & 31, wp = tid >> 5;
    if (lane == 0)
        #pragma unroll
        for (int i = 0; i < 8; i++) red[wp*8 + i] = v8[i];
    __syncthreads();
    if (tid < 8) {
        float r = 0.f;
        #pragma unroll
        for (int wq = 0; wq < 8; wq++) r += red[wq*8 + tid];
        if (tid < 4) g_p1s[(cbase + tid)*NB + n] = r;
        else         g_p1q[(cbase + tid - 4)*NB + n] = r;
    }
}

// ---------------- K2: conv2 (24->24) + inline BN1 finalize ----------------
// grid (6 oc-groups, 32 n), 256 threads
extern "C" __global__ void __launch_bounds__(256)
conv2_k(const float* __restrict__ w, const float* __restrict__ b,
        const float* __restrict__ bn1_g, const float* __restrict__ bn1_b) {
    extern __shared__ float sm[];
    float* sinp = sm;                 // 24 * 1089 padded planes
    float* sw   = sm + 24*1089;       // 864
    float* sa   = sw + 864;           // 24
    float* sc   = sa + 24;            // 24
    const int tid = threadIdx.x;
    const int cg = blockIdx.x, n = blockIdx.y;
    const int cbase = cg * 4;

    // inline BN1 finalize (replaces bnfin launch): threads 0..23
    if (tid < 24) {
        float s0=0,s1=0,s2=0,s3=0, q0=0,q1=0,q2=0,q3=0;
        #pragma unroll
        for (int m = 0; m < NB; m += 4) {
            s0 += g_p1s[tid*NB + m];   q0 += g_p1q[tid*NB + m];
            s1 += g_p1s[tid*NB + m+1]; q1 += g_p1q[tid*NB + m+1];
            s2 += g_p1s[tid*NB + m+2]; q2 += g_p1q[tid*NB + m+2];
            s3 += g_p1s[tid*NB + m+3]; q3 += g_p1q[tid*NB + m+3];
        }
        float s = (s0+s1)+(s2+s3), q = (q0+q1)+(q2+q3);
        float mu  = s * (1.f/32768.f);
        float var = q * (1.f/32768.f) - mu*mu;
        float a   = rsqrtf(var + 1e-5f) * bn1_g[tid];
        sa[tid] = a;
        sc[tid] = bn1_b[tid] - mu * a;
    }
    for (int i = tid; i < 1560; i += 256) {           // zero pad borders
        int pl = i / 65, r = i - pl * 65;
        if (r < 33) sinp[pl*1089 + r] = 0.f;
        else        sinp[pl*1089 + (r-32)*33] = 0.f;
    }
    for (int i = tid; i < 864; i += 256) sw[i] = w[cbase*216 + i];
    __syncthreads();   // sa/sc + pads ready

    const float* y1 = g_y1 + (size_t)n * SD * 1024;
    for (int i = tid; i < SD*1024; i += 256) {
        int c = i >> 10, rem = i & 1023;
        int y = rem >> 5, x = rem & 31;
        float v = fmaxf(fmaf(y1[i], sa[c], sc[c]), 0.f);  // BN1 + ReLU
        sinp[c*1089 + (y+1)*33 + x + 1] = v;
    }
    __syncthreads();

    int oy = tid >> 4, ox = tid & 15;     // one output position per thread
    float acc[4];
    #pragma unroll
    for (int oc = 0; oc < 4; oc++) acc[oc] = b[cbase + oc];
    #pragma unroll 4
    for (int ic = 0; ic < SD; ic++) {
        const float* sp = sinp + ic*1089 + (2*oy)*33 + 2*ox;
        float in[9];
        #pragma unroll
        for (int ky = 0; ky < 3; ky++)
            #pragma unroll
            for (int kx = 0; kx < 3; kx++) in[ky*3 + kx] = sp[ky*33 + kx];
        #pragma unroll
        for (int oc = 0; oc < 4; oc++) {
            const float* wp = sw + oc*216 + ic*9;
            #pragma unroll
            for (int t = 0; t < 9; t++) acc[oc] = fmaf(in[t], wp[t], acc[oc]);
        }
    }
    float ls[4], lq[4];
    #pragma unroll
    for (int oc = 0; oc < 4; oc++) {
        g_y2[(size_t)(n*SD + cbase + oc)*256 + tid] = acc[oc];
        ls[oc] = acc[oc]; lq[oc] = acc[oc]*acc[oc];
    }
    __shared__ float red[64];
    float v8[8] = {ls[0],ls[1],ls[2],ls[3], lq[0],lq[1],lq[2],lq[3]};
    #pragma unroll
    for (int i = 0; i < 8; i++) {
        float v = v8[i];
        #pragma unroll
        for (int o = 16; o; o >>= 1) v += __shfl_down_sync(0xffffffffu, v, o);
        v8[i] = v;
    }
    int lane = tid & 31, wp2 = tid >> 5;
    if (lane == 0)
        #pragma unroll
        for (int i = 0; i < 8; i++) red[wp2*8 + i] = v8[i];
    __syncthreads();
    if (tid < 8) {
        float r = 0.f;
        #pragma unroll
        for (int wq = 0; wq < 8; wq++) r += red[wq*8 + tid];
        if (tid < 4) g_p2s[(cbase + tid)*NB + n] = r;
        else         g_p2q[(cbase + tid - 4)*NB + n] = r;
    }
}

// ---------------- K3: inline BN2 + channel sums + rel + fc1(relu) + fc2 ----
// grid 32 (per n), 1024 threads
extern "C" __global__ void __launch_bounds__(1024)
relfc_k(const float* __restrict__ ques,  const float* __restrict__ w_rel,
        const float* __restrict__ b_rel, const float* __restrict__ bn2_g,
        const float* __restrict__ bn2_b, const float* __restrict__ w_fc1,
        const float* __restrict__ b_fc1, const float* __restrict__ w_fc2,
        const float* __restrict__ b_fc2, float* __restrict__ out) {
    __shared__ float sa[24], sc[24];
    __shared__ float s[26];
    __shared__ float q[RQ];
    __shared__ float prel[8*MD];
    __shared__ float rel[MD];
    __shared__ float r0[32], r1[32];
    const int n = blockIdx.x, tid = threadIdx.x;
    const int lane = tid & 31, wp = tid >> 5;

    // inline BN2 finalize: threads 0..23
    if (tid < 24) {
        float s0=0,s1=0,s2=0,s3=0, q0=0,q1=0,q2=0,q3=0;
        #pragma unroll
        for (int m = 0; m < NB; m += 4) {
            s0 += g_p2s[tid*NB + m];   q0 += g_p2q[tid*NB + m];
            s1 += g_p2s[tid*NB + m+1]; q1 += g_p2q[tid*NB + m+1];
            s2 += g_p2s[tid*NB + m+2]; q2 += g_p2q[tid*NB + m+2];
            s3 += g_p2s[tid*NB + m+3]; q3 += g_p2q[tid*NB + m+3];
        }
        float ss = (s0+s1)+(s2+s3), qq = (q0+q1)+(q2+q3);
        float mu  = ss * (1.f/8192.f);
        float var = qq * (1.f/8192.f) - mu*mu;
        float a   = rsqrtf(var + 1e-5f) * bn2_g[tid];
        sa[tid] = a;
        sc[tid] = bn2_b[tid] - mu * a;
    }
    if (tid >= 128 && tid < 256) q[tid - 128] = ques[n*RQ + tid - 128];
    if (tid == 24) { s[24] = 0.f; s[25] = 0.f; }   // coords sum to 0
    __syncthreads();

    // channel sums with BN2+ReLU fused: warp wp handles channel wp (<24)
    if (wp < SD) {
        const float* yp = g_y2 + (size_t)(n*SD + wp)*256;
        float a = sa[wp], sh = sc[wp];
        float v = 0.f;
        #pragma unroll
        for (int i = 0; i < 8; i++)
            v += fmaxf(fmaf(yp[lane + i*32], a, sh), 0.f);
        #pragma unroll
        for (int o = 16; o; o >>= 1) v += __shfl_down_sync(0xffffffffu, v, o);
        if (lane == 0) s[wp] = v;
    }
    __syncthreads();

    // rel partials over ques@Wq: 8 k-slices x 128 j (coalesced w_rel rows)
    {
        const int j = tid & 127, slice = tid >> 7;    // slice 0..7
        float part = 0.f;
        #pragma unroll
        for (int kk = 0; kk < 16; kk++) {
            int k = slice*16 + kk;
            part = fmaf(q[k], w_rel[(52 + k)*MD + j], part);  // Wq rows 52..179
        }
        prel[slice*MD + j] = part;
    }
    __syncthreads();
    if (tid < MD) {
        float r = b_rel[tid];
        #pragma unroll
        for (int sl = 0; sl < 8; sl++) r += prel[sl*MD + tid];
        float t = 0.f;
        #pragma unroll
        for (int c = 0; c < 26; c++)
            t = fmaf(s[c], w_rel[c*MD + tid] + w_rel[(26 + c)*MD + tid], t);
        rel[tid] = fmaf(65536.f, r, 256.f * t);
    }
    __syncthreads();

    // fc1 (relu) + fc2: one fc1 output per thread, block-reduce fc2
    float h = b_fc1[tid];
    #pragma unroll 16
    for (int k = 0; k < MD; k++)
        h = fmaf(rel[k], w_fc1[k*FC + tid], h);      // coalesced across tid
    h = fmaxf(h, 0.f);
    float a0 = h * w_fc2[tid*2 + 0];
    float a1 = h * w_fc2[tid*2 + 1];
    #pragma unroll
    for (int o = 16; o; o >>= 1) {
        a0 += __shfl_down_sync(0xffffffffu, a0, o);
        a1 += __shfl_down_sync(0xffffffffu, a1, o);
    }
    if (lane == 0) { r0[wp] = a0; r1[wp] = a1; }
    __syncthreads();
    if (tid < 32) {
        float v0 = r0[tid], v1 = r1[tid];
        #pragma unroll
        for (int o = 16; o; o >>= 1) {
            v0 += __shfl_down_sync(0xffffffffu, v0, o);
            v1 += __shfl_down_sync(0xffffffffu, v1, o);
        }
        if (tid == 0) {
            out[n*2 + 0] = v0 + b_fc2[0];
            out[n*2 + 1] = v1 + b_fc2[1];
        }
    }
}

// ---------------- launch ----------------------------------------------------
extern "C" void kernel_launch(void* const* d_in, const int* in_sizes, int n_in,
                              void* d_out, int out_size) {
    const float* image   = (const float*)d_in[0];
    const float* ques    = (const float*)d_in[1];
    const float* conv1_w = (const float*)d_in[2];
    const float* conv1_b = (const float*)d_in[3];
    const float* bn1_g   = (const float*)d_in[4];
    const float* bn1_b   = (const float*)d_in[5];
    const float* conv2_w = (const float*)d_in[6];
    const float* conv2_b = (const float*)d_in[7];
    const float* bn2_g   = (const float*)d_in[8];
    const float* bn2_b   = (const float*)d_in[9];
    const float* w_rel   = (const float*)d_in[10];
    const float* b_rel   = (const float*)d_in[11];
    const float* w_fc1   = (const float*)d_in[12];
    const float* b_fc1   = (const float*)d_in[13];
    const float* w_fc2   = (const float*)d_in[14];
    const float* b_fc2   = (const float*)d_in[15];

    const int SM1 = (3*4225 + 108 + 4) * 4;        // 51148 B
    const int SM3 = (24*1089 + 864 + 48) * 4;      // 108192 B
    cudaFuncSetAttribute(conv1_k, cudaFuncAttributeMaxDynamicSharedMemorySize, SM1);
    cudaFuncSetAttribute(conv2_k, cudaFuncAttributeMaxDynamicSharedMemorySize, SM3);

    conv1_k<<<dim3(6, 32), 256, SM1>>>(image, conv1_w, conv1_b);
    conv2_k<<<dim3(6, 32), 256, SM3>>>(conv2_w, conv2_b, bn1_g, bn1_b);
    relfc_k<<<32, 1024>>>(ques, w_rel, b_rel, bn2_g, bn2_b,
                          w_fc1, b_fc1, w_fc2, b_fc2, (float*)d_out);
}